// round 15
// baseline (speedup 1.0000x reference)
#include <cuda_runtime.h>
#include <cuda_bf16.h>
#include <cstdint>

#define Nn 64
#define Cc 192
#define HW 4096
#define TOTAL (Nn * Cc * HW)
#define NPB 2048                 // pw blocks: 32 pixel tiles * 64 images

// Scratch (cudaMalloc forbidden -> static device arrays).
__device__ float g_y[TOTAL];           // dw output, pre-rounded to tf32
__device__ float g_pw_tf[Cc * Cc];     // pw weights, tf32 + k-pair interleaved
__device__ float g_pb[Cc * NPB];       // per-block per-channel partial sums
__device__ float g_pbq[Cc * NPB];      // per-block per-channel partial sumsq

// ===========================================================================
// Helpers
// ===========================================================================
__device__ __forceinline__ uint32_t f2tf(float f) {
    uint32_t r;
    asm("cvt.rna.tf32.f32 %0, %1;" : "=r"(r) : "f"(f));
    return r;
}

__device__ __forceinline__ uint32_t smem_u32(const void* p) {
    uint32_t a;
    asm("{ .reg .u64 t; cvta.to.shared.u64 t, %1; cvt.u32.u64 %0, t; }"
        : "=r"(a) : "l"(p));
    return a;
}

#define CP_ASYNC16(dst, src) \
    asm volatile("cp.async.cg.shared.global [%0], [%1], 16;" \
                 :: "r"(dst), "l"(src) : "memory")
#define CP_COMMIT() asm volatile("cp.async.commit_group;" ::: "memory")
#define CP_WAIT(n)  asm volatile("cp.async.wait_group %0;" :: "n"(n) : "memory")

__device__ __forceinline__ void mma_tf32(float& c0, float& c1, float& c2, float& c3,
                                         uint32_t a0, uint32_t a1, uint32_t a2, uint32_t a3,
                                         uint32_t b0, uint32_t b1) {
    asm volatile(
        "mma.sync.aligned.m16n8k8.row.col.f32.tf32.tf32.f32 "
        "{%0,%1,%2,%3}, {%4,%5,%6,%7}, {%8,%9}, {%0,%1,%2,%3};"
        : "+f"(c0), "+f"(c1), "+f"(c2), "+f"(c3)
        : "r"(a0), "r"(a1), "r"(a2), "r"(a3), "r"(b0), "r"(b1));
}

// ---------------------------------------------------------------------------
// Kernel 0: pre-round pw weights to tf32 AND permute columns within each
// 8-group to [k0,k4,k1,k5,k2,k6,k3,k7] so (k, k+4) frag pairs are adjacent.
// ---------------------------------------------------------------------------
__global__ __launch_bounds__(256) void pwround_kernel(const float* __restrict__ pw) {
    const int i = blockIdx.x * 256 + threadIdx.x;
    if (i < Cc * Cc) {
        const int row = i / Cc;
        const int col = i % Cc;
        const int b = col & 7;
        const int nc = (col & ~7) | ((b & 3) * 2 + (b >> 2));
        g_pw_tf[row * Cc + nc] = __uint_as_float(f2tf(pw[i]));
    }
}

// ---------------------------------------------------------------------------
// Kernel 1: ReLU + depthwise dilated 3x3 conv; fully branch-free inner loop.
// Smem plane [68][72]: rows 0-1 / 66-67 and cols 0-3 / 68-71 are zero guards.
// Data (r, c) lives at smem[r+2][c+4]. All 9 taps are unconditional LDS.128;
// zero taps contribute fma(w, 0, acc) which is exact.
// ---------------------------------------------------------------------------
__global__ __launch_bounds__(256) void dw_kernel(const float* __restrict__ x,
                                                 const float* __restrict__ dw_w) {
    const int plane = blockIdx.x;      // n * Cc + c
    const int c = plane % Cc;
    const float* __restrict__ xp = x + (size_t)plane * HW;
    float* __restrict__ yp = g_y + (size_t)plane * HW;

    __shared__ float sm[68][72];       // 19.1 KB
    const int tid = threadIdx.x;

    // Zero guard rows (4 rows x 18 f4 = 72 f4) and column guards (64 x 2 f4).
    for (int i = tid; i < 72; i += 256) {
        const int rr = i / 18;                 // 0..3 -> rows 0,1,66,67
        const int r = (rr < 2) ? rr : 64 + rr;
        *(float4*)&sm[r][(i % 18) * 4] = make_float4(0.f, 0.f, 0.f, 0.f);
    }
    for (int i = tid; i < 128; i += 256) {
        const int r = 2 + (i >> 1);
        const int side = (i & 1) ? 68 : 0;
        *(float4*)&sm[r][side] = make_float4(0.f, 0.f, 0.f, 0.f);
    }
    // Stage plane with ReLU, float4 (1024 f4); data row r -> smem row r+2.
    for (int j = tid; j < 1024; j += 256) {
        float4 v = *(const float4*)(xp + j * 4);
        v.x = fmaxf(v.x, 0.f); v.y = fmaxf(v.y, 0.f);
        v.z = fmaxf(v.z, 0.f); v.w = fmaxf(v.w, 0.f);
        *(float4*)&sm[(j >> 4) + 2][4 + ((j & 15) << 2)] = v;
    }
    __syncthreads();

    float wv[9];
#pragma unroll
    for (int i = 0; i < 9; i++) wv[i] = dw_w[c * 9 + i];

    // 1024 groups of 4 outputs; 4 groups per thread; no bounds checks.
#pragma unroll
    for (int gi = 0; gi < 4; gi++) {
        const int g4 = tid + gi * 256;
        const int h = g4 >> 4;
        const int w0 = (g4 & 15) << 2;         // data col of first output
        float r0 = 0.f, r1 = 0.f, r2 = 0.f, r3 = 0.f;
#pragma unroll
        for (int kh = 0; kh < 3; kh++) {
            const int sr = h + 2 * kh;         // smem row = (h - 2 + 2kh) + 2
            const float4 A = *(const float4*)&sm[sr][w0];
            const float4 B = *(const float4*)&sm[sr][w0 + 4];
            const float4 C = *(const float4*)&sm[sr][w0 + 8];
            const float wa = wv[kh * 3 + 0];
            const float wb = wv[kh * 3 + 1];
            const float wc = wv[kh * 3 + 2];
            r0 = fmaf(wa, A.z, fmaf(wb, B.x, fmaf(wc, B.z, r0)));
            r1 = fmaf(wa, A.w, fmaf(wb, B.y, fmaf(wc, B.w, r1)));
            r2 = fmaf(wa, B.x, fmaf(wb, B.z, fmaf(wc, C.x, r2)));
            r3 = fmaf(wa, B.y, fmaf(wb, B.w, fmaf(wc, C.y, r3)));
        }
        float4 o;
        o.x = __uint_as_float(f2tf(r0));
        o.y = __uint_as_float(f2tf(r1));
        o.z = __uint_as_float(f2tf(r2));
        o.w = __uint_as_float(f2tf(r3));
        *(float4*)(yp + h * 64 + w0) = o;
    }
}

// ---------------------------------------------------------------------------
// Kernel 2: pointwise 1x1 conv as TF32 mma.sync GEMM + fused stats partials.
// Block tile: M=192 (ALL out channels) x N=128 pixels, K=192 in 6 chunks of 32.
// 512 threads = 16 warps as 4(m) x 4(n); warp tile 48x32 (3x4 m16n8k8).
// Weights (A, k-pair interleaved) fully resident; B double-buffered cp.async.
// ---------------------------------------------------------------------------
#define AS_W 200      // AS_W/2 = 100 == 4 mod 16 -> float2 frag loads conflict-free
#define BS_W 136      // 136 % 32 == 8 -> b-frag banks (8t+g) distinct
#define SM_A    0
#define SM_B0   (192 * AS_W * 4)                 // 153600
#define SM_B1   (SM_B0 + 32 * BS_W * 4)          // +17408
#define SM_SUM  (SM_B1 + 32 * BS_W * 4)          // 188416
#define SM_SUMQ (SM_SUM + 4 * Cc * 4)            // +3072
#define SM_TOT  (SM_SUMQ + 4 * Cc * 4)           // 194560 bytes

__global__ __launch_bounds__(512)
void pw_mma2_kernel(float* __restrict__ zout) {
    extern __shared__ char smem[];
    const uint32_t sb = smem_u32(smem);
    const int tid = threadIdx.x;
    const int wid = tid >> 5;
    const int lane = tid & 31;
    const int g = lane >> 2;          // 0..7
    const int t = lane & 3;           // 0..3
    const int warp_m = (wid >> 2) * 48;   // 0,48,96,144
    const int wn = wid & 3;
    const int warp_n = wn * 32;           // 0,32,64,96

    const int px = blockIdx.x;            // pixel tile (0..31)
    const int n = blockIdx.y;             // image
    const int p_block = px * 128;
    const int bid = n * 32 + px;          // 0..2047
    const float* __restrict__ Y = g_y + (size_t)n * Cc * HW;
    float* __restrict__ Z = zout + (size_t)n * Cc * HW;

    // ---- Prologue: cp.async full weight matrix A [192][192] (stride 200) ----
#pragma unroll
    for (int it = 0; it < 18; it++) {
        const int idx = tid + it * 512;          // 0..9215 float4s
        const int row = idx / 48;
        const int c4 = (idx % 48) * 4;
        CP_ASYNC16(sb + SM_A + (uint32_t)(row * AS_W + c4) * 4u,
                   g_pw_tf + row * Cc + c4);
    }
    // ---- B chunk 0 and 1 (each its own group) ----
#pragma unroll
    for (int it = 0; it < 2; it++) {
        const int idx = tid + it * 512;          // 0..1023
        const int row = idx >> 5;                // 0..31
        const int c4 = (idx & 31) * 4;
        CP_ASYNC16(sb + SM_B0 + (uint32_t)(row * BS_W + c4) * 4u,
                   Y + (size_t)row * HW + p_block + c4);
    }
    CP_COMMIT();   // group0: A + B0
#pragma unroll
    for (int it = 0; it < 2; it++) {
        const int idx = tid + it * 512;
        const int row = idx >> 5;
        const int c4 = (idx & 31) * 4;
        CP_ASYNC16(sb + SM_B1 + (uint32_t)(row * BS_W + c4) * 4u,
                   Y + (size_t)(32 + row) * HW + p_block + c4);
    }
    CP_COMMIT();   // group1: B1

    const float* As = (const float*)(smem + SM_A);

    float acc[3][4][4];
#pragma unroll
    for (int i = 0; i < 3; i++)
#pragma unroll
        for (int j = 0; j < 4; j++)
#pragma unroll
            for (int q = 0; q < 4; q++) acc[i][j][q] = 0.0f;

    for (int ch = 0; ch < 6; ch++) {
        if (ch < 5) { CP_WAIT(1); } else { CP_WAIT(0); }
        __syncthreads();

        const int kc = ch * 32;
        const float* Bs = (const float*)(smem + ((ch & 1) ? SM_B1 : SM_B0));

#pragma unroll
        for (int ks = 0; ks < 32; ks += 8) {
            uint32_t a[3][4], b[4][2];
            const int kk = kc + ks;      // interleaved: (k=t, k=t+4) at kk+2t
#pragma unroll
            for (int mt = 0; mt < 3; mt++) {
                const int r0 = warp_m + mt * 16 + g;
                const float2 af0 = *(const float2*)&As[r0 * AS_W + kk + 2 * t];
                const float2 af1 = *(const float2*)&As[(r0 + 8) * AS_W + kk + 2 * t];
                a[mt][0] = __float_as_uint(af0.x);
                a[mt][1] = __float_as_uint(af1.x);
                a[mt][2] = __float_as_uint(af0.y);
                a[mt][3] = __float_as_uint(af1.y);
            }
#pragma unroll
            for (int nt = 0; nt < 4; nt++) {
                const int nc = warp_n + nt * 8 + g;
                b[nt][0] = __float_as_uint(Bs[(ks + t) * BS_W + nc]);
                b[nt][1] = __float_as_uint(Bs[(ks + t + 4) * BS_W + nc]);
            }
#pragma unroll
            for (int mt = 0; mt < 3; mt++)
#pragma unroll
                for (int nt = 0; nt < 4; nt++)
                    mma_tf32(acc[mt][nt][0], acc[mt][nt][1],
                             acc[mt][nt][2], acc[mt][nt][3],
                             a[mt][0], a[mt][1], a[mt][2], a[mt][3],
                             b[nt][0], b[nt][1]);
        }
        __syncthreads();    // buffer (ch&1) free for refill

        if (ch + 2 < 6) {
            const int nk = ch + 2;
            const uint32_t boff = (nk & 1) ? SM_B1 : SM_B0;
#pragma unroll
            for (int it = 0; it < 2; it++) {
                const int idx = tid + it * 512;
                const int row = idx >> 5;
                const int c4 = (idx & 31) * 4;
                CP_ASYNC16(sb + boff + (uint32_t)(row * BS_W + c4) * 4u,
                           Y + (size_t)(nk * 32 + row) * HW + p_block + c4);
            }
            CP_COMMIT();
        }
    }

    // ---- Store z + accumulate per-channel partial sums over this tile ----
    float s[3][2], q[3][2];
#pragma unroll
    for (int mt = 0; mt < 3; mt++) { s[mt][0] = s[mt][1] = q[mt][0] = q[mt][1] = 0.0f; }

#pragma unroll
    for (int mt = 0; mt < 3; mt++) {
        const int r0 = warp_m + mt * 16 + g;
#pragma unroll
        for (int nt = 0; nt < 4; nt++) {
            const int col = p_block + warp_n + nt * 8 + 2 * t;
            const float c0 = acc[mt][nt][0], c1 = acc[mt][nt][1];
            const float c2 = acc[mt][nt][2], c3 = acc[mt][nt][3];
            *(float2*)(Z + (size_t)r0 * HW + col) = make_float2(c0, c1);
            *(float2*)(Z + (size_t)(r0 + 8) * HW + col) = make_float2(c2, c3);
            s[mt][0] += c0 + c1;           q[mt][0] += c0 * c0 + c1 * c1;
            s[mt][1] += c2 + c3;           q[mt][1] += c2 * c2 + c3 * c3;
        }
    }
    // reduce over the 4 lanes of each quad (fixed order -> deterministic)
#pragma unroll
    for (int off = 1; off < 4; off <<= 1) {
#pragma unroll
        for (int mt = 0; mt < 3; mt++) {
#pragma unroll
            for (int h = 0; h < 2; h++) {
                s[mt][h] += __shfl_xor_sync(0xffffffffu, s[mt][h], off);
                q[mt][h] += __shfl_xor_sync(0xffffffffu, q[mt][h], off);
            }
        }
    }
    float* sums = (float*)(smem + SM_SUM);     // [4][192]
    float* sumq = (float*)(smem + SM_SUMQ);    // [4][192]
    if (t == 0) {
#pragma unroll
        for (int mt = 0; mt < 3; mt++) {
            const int r0 = warp_m + mt * 16 + g;
            sums[wn * Cc + r0] = s[mt][0];
            sums[wn * Cc + r0 + 8] = s[mt][1];
            sumq[wn * Cc + r0] = q[mt][0];
            sumq[wn * Cc + r0 + 8] = q[mt][1];
        }
    }
    __syncthreads();
    if (tid < Cc) {
        float ts = 0.0f, tq = 0.0f;
#pragma unroll
        for (int w = 0; w < 4; w++) { ts += sums[w * Cc + tid]; tq += sumq[w * Cc + tid]; }
        g_pb[tid * NPB + bid] = ts;
        g_pbq[tid * NPB + bid] = tq;
    }
}

// ---------------------------------------------------------------------------
// Kernel 3: fused stats-finalize + BN normalize.
// Grid (Cc, 8): block (c, sl) deterministically reduces channel c's 2048
// partials (double accum, same order in every block for the same c), then
// normalizes z for channel c over images sl*8 .. sl*8+7.
// ---------------------------------------------------------------------------
__global__ __launch_bounds__(256) void bnfuse_kernel(float* __restrict__ z,
                                                     const float* __restrict__ gamma,
                                                     const float* __restrict__ beta) {
    const int c = blockIdx.x;
    const int sl = blockIdx.y;
    const int tid = threadIdx.x;

    // Reduce this channel's partials (8 consecutive per thread, then tree).
    const float* __restrict__ pb = g_pb + c * NPB;
    const float* __restrict__ pbq = g_pbq + c * NPB;
    double s = 0.0, sq = 0.0;
#pragma unroll
    for (int j = 0; j < 8; j++) {
        const int b = tid * 8 + j;
        s += (double)pb[b];
        sq += (double)pbq[b];
    }
    __shared__ double ss[256];
    __shared__ double ssq[256];
    ss[tid] = s;
    ssq[tid] = sq;
    __syncthreads();
    for (int stride = 128; stride > 0; stride >>= 1) {
        if (tid < stride) {
            ss[tid] += ss[tid + stride];
            ssq[tid] += ssq[tid + stride];
        }
        __syncthreads();
    }
    __shared__ float mr[2];
    if (tid == 0) {
        const double inv_n = 1.0 / (double)(Nn * HW);
        const double mean = ss[0] * inv_n;
        const double var = ssq[0] * inv_n - mean * mean;
        mr[0] = (float)mean;
        mr[1] = (float)(1.0 / sqrt(var + 1e-5));
    }
    __syncthreads();

    const float gg = gamma[c] * mr[1];
    const float b = beta[c] - mr[0] * gg;

    // Normalize 8 image planes of channel c (each 4096 floats = 1024 f4).
#pragma unroll
    for (int nl = 0; nl < 8; nl++) {
        float* __restrict__ p = z + (size_t)((sl * 8 + nl) * Cc + c) * HW;
#pragma unroll
        for (int j = 0; j < 4; j++) {
            const int i = (tid + j * 256) * 4;
            float4 v = *(float4*)(p + i);
            v.x = fmaf(v.x, gg, b);
            v.y = fmaf(v.y, gg, b);
            v.z = fmaf(v.z, gg, b);
            v.w = fmaf(v.w, gg, b);
            *(float4*)(p + i) = v;
        }
    }
}

// ---------------------------------------------------------------------------
extern "C" void kernel_launch(void* const* d_in, const int* in_sizes, int n_in,
                              void* d_out, int out_size) {
    const float* x     = (const float*)d_in[0];   // (64,192,64,64)
    const float* dw_w  = (const float*)d_in[1];   // (192,1,3,3)
    const float* pw_w  = (const float*)d_in[2];   // (192,192)
    const float* gamma = (const float*)d_in[3];   // (192,)
    const float* beta  = (const float*)d_in[4];   // (192,)
    float* out = (float*)d_out;

    // 0) Pre-round + interleave weights to tf32
    pwround_kernel<<<(Cc * Cc + 255) / 256, 256>>>(pw_w);

    // 1) ReLU + depthwise dilated conv -> g_y (tf32-rounded)
    dw_kernel<<<Nn * Cc, 256>>>(x, dw_w);

    // 2) Pointwise GEMM (tf32 mma.sync, cp.async pipeline) + stats partials
    cudaFuncSetAttribute(pw_mma2_kernel,
                         cudaFuncAttributeMaxDynamicSharedMemorySize, SM_TOT);
    dim3 grid(32, Nn);
    pw_mma2_kernel<<<grid, 512, SM_TOT>>>(out);

    // 3) Fused stats-finalize + BN normalize (in place)
    bnfuse_kernel<<<dim3(Cc, 8), 256>>>(out, gamma, beta);
}

// round 17
// speedup vs baseline: 1.0104x; 1.0104x over previous
#include <cuda_runtime.h>
#include <cuda_bf16.h>
#include <cstdint>

#define Nn 64
#define Cc 192
#define HW 4096
#define TOTAL (Nn * Cc * HW)
#define NPB 2048                 // pw blocks: 32 pixel tiles * 64 images

// Scratch (cudaMalloc forbidden -> static device arrays).
__device__ float g_y[TOTAL];           // dw output, pre-rounded to tf32
__device__ float g_pw_tf[Cc * Cc];     // pw weights, tf32 + k-pair interleaved
__device__ float g_pb[Cc * NPB];       // per-block per-channel partial sums
__device__ float g_pbq[Cc * NPB];      // per-block per-channel partial sumsq

// ===========================================================================
// Helpers
// ===========================================================================
__device__ __forceinline__ uint32_t f2tf(float f) {
    uint32_t r;
    asm("cvt.rna.tf32.f32 %0, %1;" : "=r"(r) : "f"(f));
    return r;
}

__device__ __forceinline__ uint32_t smem_u32(const void* p) {
    uint32_t a;
    asm("{ .reg .u64 t; cvta.to.shared.u64 t, %1; cvt.u32.u64 %0, t; }"
        : "=r"(a) : "l"(p));
    return a;
}

#define CP_ASYNC16(dst, src) \
    asm volatile("cp.async.cg.shared.global [%0], [%1], 16;" \
                 :: "r"(dst), "l"(src) : "memory")
#define CP_COMMIT() asm volatile("cp.async.commit_group;" ::: "memory")
#define CP_WAIT(n)  asm volatile("cp.async.wait_group %0;" :: "n"(n) : "memory")

__device__ __forceinline__ void mma_tf32(float& c0, float& c1, float& c2, float& c3,
                                         uint32_t a0, uint32_t a1, uint32_t a2, uint32_t a3,
                                         uint32_t b0, uint32_t b1) {
    asm volatile(
        "mma.sync.aligned.m16n8k8.row.col.f32.tf32.tf32.f32 "
        "{%0,%1,%2,%3}, {%4,%5,%6,%7}, {%8,%9}, {%0,%1,%2,%3};"
        : "+f"(c0), "+f"(c1), "+f"(c2), "+f"(c3)
        : "r"(a0), "r"(a1), "r"(a2), "r"(a3), "r"(b0), "r"(b1));
}

// ---------------------------------------------------------------------------
// Kernel 0: pre-round pw weights to tf32 AND permute columns within each
// 8-group to [k0,k4,k1,k5,k2,k6,k3,k7] so (k, k+4) frag pairs are adjacent.
// ---------------------------------------------------------------------------
__global__ __launch_bounds__(256) void pwround_kernel(const float* __restrict__ pw) {
    const int i = blockIdx.x * 256 + threadIdx.x;
    if (i < Cc * Cc) {
        const int row = i / Cc;
        const int col = i % Cc;
        const int b = col & 7;
        const int nc = (col & ~7) | ((b & 3) * 2 + (b >> 2));
        g_pw_tf[row * Cc + nc] = __uint_as_float(f2tf(pw[i]));
    }
}

// ---------------------------------------------------------------------------
// Kernel 1: ReLU + depthwise dilated 3x3 conv (round-14 version: column guard
// pads only; cheap uniform row predicates). Output pre-rounded to tf32.
// Smem plane [64][72]: cols 0..3 / 68..71 zero guards, data col c at c+4.
// ---------------------------------------------------------------------------
__global__ __launch_bounds__(256) void dw_kernel(const float* __restrict__ x,
                                                 const float* __restrict__ dw_w) {
    const int plane = blockIdx.x;      // n * Cc + c
    const int c = plane % Cc;
    const float* __restrict__ xp = x + (size_t)plane * HW;
    float* __restrict__ yp = g_y + (size_t)plane * HW;

    __shared__ float sm[64][72];       // 18 KB
    const int tid = threadIdx.x;

    // Zero the column guards (2 float4 per row).
    for (int i = tid; i < 128; i += 256) {
        const int r = i >> 1;
        const int side = (i & 1) ? 68 : 0;
        *(float4*)&sm[r][side] = make_float4(0.f, 0.f, 0.f, 0.f);
    }
    // Stage plane with ReLU, float4 (1024 f4).
    for (int j = tid; j < 1024; j += 256) {
        float4 v = *(const float4*)(xp + j * 4);
        v.x = fmaxf(v.x, 0.f); v.y = fmaxf(v.y, 0.f);
        v.z = fmaxf(v.z, 0.f); v.w = fmaxf(v.w, 0.f);
        *(float4*)&sm[j >> 4][4 + ((j & 15) << 2)] = v;
    }
    __syncthreads();

    float wv[9];
#pragma unroll
    for (int i = 0; i < 9; i++) wv[i] = dw_w[c * 9 + i];

    // 1024 groups of 4 outputs; 4 groups per thread.
#pragma unroll
    for (int gi = 0; gi < 4; gi++) {
        const int g4 = tid + gi * 256;
        const int h = g4 >> 4;
        const int w0 = (g4 & 15) << 2;         // data col of first output
        float r0 = 0.f, r1 = 0.f, r2 = 0.f, r3 = 0.f;
#pragma unroll
        for (int kh = 0; kh < 3; kh++) {
            const int ih = h + 2 * kh - 2;
            if ((unsigned)ih < 64u) {
                const float4 A = *(const float4*)&sm[ih][w0];
                const float4 B = *(const float4*)&sm[ih][w0 + 4];
                const float4 C = *(const float4*)&sm[ih][w0 + 8];
                const float wa = wv[kh * 3 + 0];
                const float wb = wv[kh * 3 + 1];
                const float wc = wv[kh * 3 + 2];
                r0 = fmaf(wa, A.z, fmaf(wb, B.x, fmaf(wc, B.z, r0)));
                r1 = fmaf(wa, A.w, fmaf(wb, B.y, fmaf(wc, B.w, r1)));
                r2 = fmaf(wa, B.x, fmaf(wb, B.z, fmaf(wc, C.x, r2)));
                r3 = fmaf(wa, B.y, fmaf(wb, B.w, fmaf(wc, C.y, r3)));
            }
        }
        float4 o;
        o.x = __uint_as_float(f2tf(r0));
        o.y = __uint_as_float(f2tf(r1));
        o.z = __uint_as_float(f2tf(r2));
        o.w = __uint_as_float(f2tf(r3));
        *(float4*)(yp + h * 64 + w0) = o;
    }
}

// ---------------------------------------------------------------------------
// Kernel 2: pointwise 1x1 conv as TF32 mma.sync GEMM + fused stats partials.
// Block tile: M=192 (ALL out channels) x N=128 pixels, K=192 in 6 chunks of 32.
// 512 threads = 16 warps as 4(m) x 4(n); warp tile 48x32 (3x4 m16n8k8).
// Weights (A, k-pair interleaved) fully resident; B in a 3-buffer cp.async
// ring: per chunk, ONE barrier, refill issued BEFORE the chunk's MMA so each
// load has a full chunk of MMA time to land.
// ---------------------------------------------------------------------------
#define AS_W 200      // AS_W/2 = 100 == 4 mod 16 -> float2 frag loads conflict-free
#define BS_W 136      // 136 % 32 == 8 -> b-frag banks (8t+g) distinct
#define BBUF (32 * BS_W * 4)                     // 17408 bytes per B buffer
#define SM_A    0
#define SM_B    (192 * AS_W * 4)                 // 153600; 3 buffers follow
#define SM_SUM  (SM_B + 3 * BBUF)                // 205824
#define SM_SUMQ (SM_SUM + 4 * Cc * 4)            // +3072
#define SM_TOT  (SM_SUMQ + 4 * Cc * 4)           // 211968 bytes

__global__ __launch_bounds__(512)
void pw_mma2_kernel(float* __restrict__ zout) {
    extern __shared__ char smem[];
    const uint32_t sb = smem_u32(smem);
    const int tid = threadIdx.x;
    const int wid = tid >> 5;
    const int lane = tid & 31;
    const int g = lane >> 2;          // 0..7
    const int t = lane & 3;           // 0..3
    const int warp_m = (wid >> 2) * 48;   // 0,48,96,144
    const int wn = wid & 3;
    const int warp_n = wn * 32;           // 0,32,64,96

    const int px = blockIdx.x;            // pixel tile (0..31)
    const int n = blockIdx.y;             // image
    const int p_block = px * 128;
    const int bid = n * 32 + px;          // 0..2047
    const float* __restrict__ Y = g_y + (size_t)n * Cc * HW;
    float* __restrict__ Z = zout + (size_t)n * Cc * HW;

    // ---- Prologue: group0 = full A (stride 200) + B chunk 0 ----
#pragma unroll
    for (int it = 0; it < 18; it++) {
        const int idx = tid + it * 512;          // 0..9215 float4s
        const int row = idx / 48;
        const int c4 = (idx % 48) * 4;
        CP_ASYNC16(sb + SM_A + (uint32_t)(row * AS_W + c4) * 4u,
                   g_pw_tf + row * Cc + c4);
    }
#pragma unroll
    for (int it = 0; it < 2; it++) {
        const int idx = tid + it * 512;          // 0..1023
        const int row = idx >> 5;                // 0..31
        const int c4 = (idx & 31) * 4;
        CP_ASYNC16(sb + SM_B + (uint32_t)(row * BS_W + c4) * 4u,
                   Y + (size_t)row * HW + p_block + c4);
    }
    CP_COMMIT();   // group0: A + B0
    // ---- group1 = B chunk 1 ----
#pragma unroll
    for (int it = 0; it < 2; it++) {
        const int idx = tid + it * 512;
        const int row = idx >> 5;
        const int c4 = (idx & 31) * 4;
        CP_ASYNC16(sb + SM_B + BBUF + (uint32_t)(row * BS_W + c4) * 4u,
                   Y + (size_t)(32 + row) * HW + p_block + c4);
    }
    CP_COMMIT();   // group1: B1

    const float* As = (const float*)(smem + SM_A);

    float acc[3][4][4];
#pragma unroll
    for (int i = 0; i < 3; i++)
#pragma unroll
        for (int j = 0; j < 4; j++)
#pragma unroll
            for (int q = 0; q < 4; q++) acc[i][j][q] = 0.0f;

    for (int ch = 0; ch < 6; ch++) {
        // B[ch] ready when all but the most recent group are done.
        if (ch < 5) { CP_WAIT(1); } else { CP_WAIT(0); }
        __syncthreads();   // also fences last reads of buf[(ch+2)%3] (chunk ch-1)

        // Refill buffer for chunk ch+2 BEFORE computing: full chunk of overlap.
        if (ch + 2 < 6) {
            const int nk = ch + 2;
            const uint32_t boff = SM_B + (uint32_t)(nk % 3) * BBUF;
#pragma unroll
            for (int it = 0; it < 2; it++) {
                const int idx = tid + it * 512;
                const int row = idx >> 5;
                const int c4 = (idx & 31) * 4;
                CP_ASYNC16(boff + sb + (uint32_t)(row * BS_W + c4) * 4u,
                           Y + (size_t)(nk * 32 + row) * HW + p_block + c4);
            }
            CP_COMMIT();
        }

        const int kc = ch * 32;
        const float* Bs = (const float*)(smem + SM_B + (size_t)(ch % 3) * BBUF);

#pragma unroll
        for (int ks = 0; ks < 32; ks += 8) {
            uint32_t a[3][4], b[4][2];
            const int kk = kc + ks;      // interleaved: (k=t, k=t+4) at kk+2t
#pragma unroll
            for (int mt = 0; mt < 3; mt++) {
                const int r0 = warp_m + mt * 16 + g;
                const float2 af0 = *(const float2*)&As[r0 * AS_W + kk + 2 * t];
                const float2 af1 = *(const float2*)&As[(r0 + 8) * AS_W + kk + 2 * t];
                a[mt][0] = __float_as_uint(af0.x);
                a[mt][1] = __float_as_uint(af1.x);
                a[mt][2] = __float_as_uint(af0.y);
                a[mt][3] = __float_as_uint(af1.y);
            }
#pragma unroll
            for (int nt = 0; nt < 4; nt++) {
                const int nc = warp_n + nt * 8 + g;
                b[nt][0] = __float_as_uint(Bs[(ks + t) * BS_W + nc]);
                b[nt][1] = __float_as_uint(Bs[(ks + t + 4) * BS_W + nc]);
            }
#pragma unroll
            for (int mt = 0; mt < 3; mt++)
#pragma unroll
                for (int nt = 0; nt < 4; nt++)
                    mma_tf32(acc[mt][nt][0], acc[mt][nt][1],
                             acc[mt][nt][2], acc[mt][nt][3],
                             a[mt][0], a[mt][1], a[mt][2], a[mt][3],
                             b[nt][0], b[nt][1]);
        }
    }

    // ---- Store z + accumulate per-channel partial sums over this tile ----
    float s[3][2], q[3][2];
#pragma unroll
    for (int mt = 0; mt < 3; mt++) { s[mt][0] = s[mt][1] = q[mt][0] = q[mt][1] = 0.0f; }

#pragma unroll
    for (int mt = 0; mt < 3; mt++) {
        const int r0 = warp_m + mt * 16 + g;
#pragma unroll
        for (int nt = 0; nt < 4; nt++) {
            const int col = p_block + warp_n + nt * 8 + 2 * t;
            const float c0 = acc[mt][nt][0], c1 = acc[mt][nt][1];
            const float c2 = acc[mt][nt][2], c3 = acc[mt][nt][3];
            *(float2*)(Z + (size_t)r0 * HW + col) = make_float2(c0, c1);
            *(float2*)(Z + (size_t)(r0 + 8) * HW + col) = make_float2(c2, c3);
            s[mt][0] += c0 + c1;           q[mt][0] += c0 * c0 + c1 * c1;
            s[mt][1] += c2 + c3;           q[mt][1] += c2 * c2 + c3 * c3;
        }
    }
    // reduce over the 4 lanes of each quad (fixed order -> deterministic)
#pragma unroll
    for (int off = 1; off < 4; off <<= 1) {
#pragma unroll
        for (int mt = 0; mt < 3; mt++) {
#pragma unroll
            for (int h = 0; h < 2; h++) {
                s[mt][h] += __shfl_xor_sync(0xffffffffu, s[mt][h], off);
                q[mt][h] += __shfl_xor_sync(0xffffffffu, q[mt][h], off);
            }
        }
    }
    float* sums = (float*)(smem + SM_SUM);     // [4][192]
    float* sumq = (float*)(smem + SM_SUMQ);    // [4][192]
    __syncthreads();   // mainloop smem reads done before sums overlay writes
    if (t == 0) {
#pragma unroll
        for (int mt = 0; mt < 3; mt++) {
            const int r0 = warp_m + mt * 16 + g;
            sums[wn * Cc + r0] = s[mt][0];
            sums[wn * Cc + r0 + 8] = s[mt][1];
            sumq[wn * Cc + r0] = q[mt][0];
            sumq[wn * Cc + r0 + 8] = q[mt][1];
        }
    }
    __syncthreads();
    if (tid < Cc) {
        float ts = 0.0f, tq = 0.0f;
#pragma unroll
        for (int w = 0; w < 4; w++) { ts += sums[w * Cc + tid]; tq += sumq[w * Cc + tid]; }
        g_pb[tid * NPB + bid] = ts;
        g_pbq[tid * NPB + bid] = tq;
    }
}

// ---------------------------------------------------------------------------
// Kernel 3: fused stats-finalize + BN normalize.
// Grid (Cc, 8): block (c, sl) deterministically reduces channel c's 2048
// partials (double accum, same order in every block for the same c), then
// normalizes z for channel c over images sl*8 .. sl*8+7.
// ---------------------------------------------------------------------------
__global__ __launch_bounds__(256) void bnfuse_kernel(float* __restrict__ z,
                                                     const float* __restrict__ gamma,
                                                     const float* __restrict__ beta) {
    const int c = blockIdx.x;
    const int sl = blockIdx.y;
    const int tid = threadIdx.x;

    // Reduce this channel's partials (8 consecutive per thread, then tree).
    const float* __restrict__ pb = g_pb + c * NPB;
    const float* __restrict__ pbq = g_pbq + c * NPB;
    double s = 0.0, sq = 0.0;
#pragma unroll
    for (int j = 0; j < 8; j++) {
        const int b = tid * 8 + j;
        s += (double)pb[b];
        sq += (double)pbq[b];
    }
    __shared__ double ss[256];
    __shared__ double ssq[256];
    ss[tid] = s;
    ssq[tid] = sq;
    __syncthreads();
    for (int stride = 128; stride > 0; stride >>= 1) {
        if (tid < stride) {
            ss[tid] += ss[tid + stride];
            ssq[tid] += ssq[tid + stride];
        }
        __syncthreads();
    }
    __shared__ float mr[2];
    if (tid == 0) {
        const double inv_n = 1.0 / (double)(Nn * HW);
        const double mean = ss[0] * inv_n;
        const double var = ssq[0] * inv_n - mean * mean;
        mr[0] = (float)mean;
        mr[1] = (float)(1.0 / sqrt(var + 1e-5));
    }
    __syncthreads();

    const float gg = gamma[c] * mr[1];
    const float b = beta[c] - mr[0] * gg;

    // Normalize 8 image planes of channel c (each 4096 floats = 1024 f4).
#pragma unroll
    for (int nl = 0; nl < 8; nl++) {
        float* __restrict__ p = z + (size_t)((sl * 8 + nl) * Cc + c) * HW;
#pragma unroll
        for (int j = 0; j < 4; j++) {
            const int i = (tid + j * 256) * 4;
            float4 v = *(float4*)(p + i);
            v.x = fmaf(v.x, gg, b);
            v.y = fmaf(v.y, gg, b);
            v.z = fmaf(v.z, gg, b);
            v.w = fmaf(v.w, gg, b);
            *(float4*)(p + i) = v;
        }
    }
}

// ---------------------------------------------------------------------------
extern "C" void kernel_launch(void* const* d_in, const int* in_sizes, int n_in,
                              void* d_out, int out_size) {
    const float* x     = (const float*)d_in[0];   // (64,192,64,64)
    const float* dw_w  = (const float*)d_in[1];   // (192,1,3,3)
    const float* pw_w  = (const float*)d_in[2];   // (192,192)
    const float* gamma = (const float*)d_in[3];   // (192,)
    const float* beta  = (const float*)d_in[4];   // (192,)
    float* out = (float*)d_out;

    // 0) Pre-round + interleave weights to tf32
    pwround_kernel<<<(Cc * Cc + 255) / 256, 256>>>(pw_w);

    // 1) ReLU + depthwise dilated conv -> g_y (tf32-rounded)
    dw_kernel<<<Nn * Cc, 256>>>(x, dw_w);

    // 2) Pointwise GEMM (tf32 mma.sync, 3-buffer cp.async ring) + stats partials
    cudaFuncSetAttribute(pw_mma2_kernel,
                         cudaFuncAttributeMaxDynamicSharedMemorySize, SM_TOT);
    dim3 grid(32, Nn);
    pw_mma2_kernel<<<grid, 512, SM_TOT>>>(out);

    // 3) Fused stats-finalize + BN normalize (in place)
    bnfuse_kernel<<<dim3(Cc, 8), 256>>>(out, gamma, beta);
}